// round 5
// baseline (speedup 1.0000x reference)
#include <cuda_runtime.h>
#include <cstdint>

#define SQ 2048
#define DM 1024
#define NH 16
#define HD 64
#define NT (SQ / 64)  // 32 column tiles

// Scratch (allocation-free)
__device__ float g_o[SQ * DM];             // attention output O (fp32)
__device__ float g_rsum[NH * SQ];          // per-row softmax denominators
__device__ uint32_t g_qp[NH * 16 * 8192];  // Q, permuted frag layout per (h, mtile)
__device__ uint32_t g_kp[NH * 32 * 4096];  // K, permuted per (h, ttile)
__device__ uint32_t g_vp[NH * 32 * 4096];  // V^T, permuted per (h, ttile)

__device__ __forceinline__ uint32_t f2tf(float f) {
    uint32_t u;
    asm("cvt.rna.tf32.f32 %0, %1;" : "=r"(u) : "f"(f));
    return u;
}

__device__ __forceinline__ void mma8(float* c, uint32_t a0, uint32_t a1, uint32_t a2,
                                     uint32_t a3, uint32_t b0, uint32_t b1) {
    asm("mma.sync.aligned.m16n8k8.row.col.f32.tf32.tf32.f32 "
        "{%0,%1,%2,%3},{%4,%5,%6,%7},{%8,%9},{%0,%1,%2,%3};"
        : "+f"(c[0]), "+f"(c[1]), "+f"(c[2]), "+f"(c[3])
        : "r"(a0), "r"(a1), "r"(a2), "r"(a3), "r"(b0), "r"(b1));
}

// Permuted fragment-major smem/global layout (one LDS.128 per mma fragment).
__device__ __forceinline__ int perm_word(int NS, int r, int k) {
    int gg = r & 7;
    int kk = k & 7;
    int L = gg * 4 + ((kk & 3) ^ (gg & 3));
    return (((r >> 4) * NS + (k >> 3)) * 32 + L) * 4 + ((r >> 3) & 1) + 2 * (kk >> 2);
}
__device__ __forceinline__ void sts_perm4(uint32_t* S, int NS, int r, int c4, uint4 u) {
    int gg = r & 7;
    int base = (((r >> 4) * NS + (c4 >> 3)) * 32 + gg * 4) * 4 + ((r >> 3) & 1) +
               2 * ((c4 >> 2) & 1);
    int x = gg & 3;
    S[base + (0 ^ x) * 4] = u.x;
    S[base + (1 ^ x) * 4] = u.y;
    S[base + (2 ^ x) * 4] = u.z;
    S[base + (3 ^ x) * 4] = u.w;
}
__device__ __forceinline__ int frag_addr(int NS, int band, int s, int g, int t4) {
    return ((band * NS + s) * 32 + g * 4 + (t4 ^ (g & 3))) * 4;
}

__device__ __forceinline__ void cpa16(void* dst, const void* src) {
    uint32_t s = (uint32_t)__cvta_generic_to_shared(dst);
    asm volatile("cp.async.cg.shared.global [%0], [%1], 16;" ::"r"(s), "l"(src));
}
#define CPA_COMMIT asm volatile("cp.async.commit_group;")
#define CPA_WAIT(n) asm volatile("cp.async.wait_group %0;" ::"n"(n))

// ---------------------------------------------------------------------------
// QKV projections, z-batched (z=0:Q, 1:K, 2:V). C = A @ W^T, tf32-rounded,
// written in the permuted fragment layout. Double-buffered, 1 sync per k-tile.
// ---------------------------------------------------------------------------
__global__ __launch_bounds__(256) void gemm_qkv(
    const float* __restrict__ q_in, const float* __restrict__ k_in,
    const float* __restrict__ v_in, const float* __restrict__ Wq,
    const float* __restrict__ Wk, const float* __restrict__ Wv) {
    const int z = blockIdx.z;
    const float* A = z == 0 ? q_in : z == 1 ? k_in : v_in;
    const float* B = z == 0 ? Wq : z == 1 ? Wk : Wv;
    uint32_t* D = z == 0 ? g_qp : z == 1 ? g_kp : g_vp;

    __shared__ uint32_t Ap[2][4096];  // 128 x 32 each
    __shared__ uint32_t Bp[2][2048];  // 64 x 32 each
    const int tid = threadIdx.x, lane = tid & 31, wid = tid >> 5;
    const int g = lane >> 2, t4 = lane & 3;
    const int wm = (wid & 1) * 64, wn = (wid >> 1) * 16;
    const int m0 = blockIdx.y * 128, n0 = blockIdx.x * 64;

    float acc[4][2][4] = {};
    float4 pa[4], pb[2];

#pragma unroll
    for (int i = 0; i < 4; i++) {
        int idx = tid + i * 256, r = idx >> 3, c4 = (idx & 7) * 4;
        pa[i] = *(const float4*)(A + (m0 + r) * DM + c4);
    }
#pragma unroll
    for (int i = 0; i < 2; i++) {
        int idx = tid + i * 256, r = idx >> 3, c4 = (idx & 7) * 4;
        pb[i] = *(const float4*)(B + (n0 + r) * DM + c4);
    }
#pragma unroll
    for (int i = 0; i < 4; i++) {
        int idx = tid + i * 256, r = idx >> 3, c4 = (idx & 7) * 4;
        uint4 u = {f2tf(pa[i].x), f2tf(pa[i].y), f2tf(pa[i].z), f2tf(pa[i].w)};
        sts_perm4(Ap[0], 4, r, c4, u);
    }
#pragma unroll
    for (int i = 0; i < 2; i++) {
        int idx = tid + i * 256, r = idx >> 3, c4 = (idx & 7) * 4;
        uint4 u = {f2tf(pb[i].x), f2tf(pb[i].y), f2tf(pb[i].z), f2tf(pb[i].w)};
        sts_perm4(Bp[0], 4, r, c4, u);
    }
    __syncthreads();

    for (int kt = 0; kt < DM / 32; kt++) {
        const int cur = kt & 1;
        if (kt + 1 < DM / 32) {
            int k0 = (kt + 1) * 32;
#pragma unroll
            for (int i = 0; i < 4; i++) {
                int idx = tid + i * 256, r = idx >> 3, c4 = (idx & 7) * 4;
                pa[i] = *(const float4*)(A + (m0 + r) * DM + k0 + c4);
            }
#pragma unroll
            for (int i = 0; i < 2; i++) {
                int idx = tid + i * 256, r = idx >> 3, c4 = (idx & 7) * 4;
                pb[i] = *(const float4*)(B + (n0 + r) * DM + k0 + c4);
            }
        }
#pragma unroll
        for (int s = 0; s < 4; s++) {
            uint4 av[4];
#pragma unroll
            for (int mi = 0; mi < 4; mi++)
                av[mi] = *(const uint4*)&Ap[cur][frag_addr(4, (wm >> 4) + mi, s, g, t4)];
            uint4 bv = *(const uint4*)&Bp[cur][frag_addr(4, wn >> 4, s, g, t4)];
#pragma unroll
            for (int mi = 0; mi < 4; mi++) {
                mma8(acc[mi][0], av[mi].x, av[mi].y, av[mi].z, av[mi].w, bv.x, bv.z);
                mma8(acc[mi][1], av[mi].x, av[mi].y, av[mi].z, av[mi].w, bv.y, bv.w);
            }
        }
        if (kt + 1 < DM / 32) {
#pragma unroll
            for (int i = 0; i < 4; i++) {
                int idx = tid + i * 256, r = idx >> 3, c4 = (idx & 7) * 4;
                uint4 u = {f2tf(pa[i].x), f2tf(pa[i].y), f2tf(pa[i].z), f2tf(pa[i].w)};
                sts_perm4(Ap[cur ^ 1], 4, r, c4, u);
            }
#pragma unroll
            for (int i = 0; i < 2; i++) {
                int idx = tid + i * 256, r = idx >> 3, c4 = (idx & 7) * 4;
                uint4 u = {f2tf(pb[i].x), f2tf(pb[i].y), f2tf(pb[i].z), f2tf(pb[i].w)};
                sts_perm4(Bp[cur ^ 1], 4, r, c4, u);
            }
        }
        __syncthreads();
    }

    const int h = blockIdx.x, by = blockIdx.y;
#pragma unroll
    for (int mi = 0; mi < 4; mi++)
#pragma unroll
        for (int ni = 0; ni < 2; ni++)
#pragma unroll
            for (int e = 0; e < 4; e++) {
                int row = wm + mi * 16 + g + ((e >> 1) * 8);  // 0..127 (m rel)
                int col = wn + ni * 8 + t4 * 2 + (e & 1);     // 0..63  (d rel)
                uint32_t val = f2tf(acc[mi][ni][e]);
                int idx;
                if (z == 0) {
                    idx = (h * 16 + by) * 8192 + perm_word(8, row, col);
                } else {
                    int tile = by * 2 + (row >> 6);
                    int r64 = row & 63;
                    idx = (h * 32 + tile) * 4096 +
                          (z == 1 ? perm_word(8, r64, col) : perm_word(8, col, r64));
                }
                D[idx] = val;
            }
}

// ---------------------------------------------------------------------------
// Output projection: out = O @ Wo^T. Double-buffered, 1 sync per k-tile.
// ---------------------------------------------------------------------------
__global__ __launch_bounds__(256) void gemm_out(const float* __restrict__ B,
                                                float* __restrict__ C) {
    __shared__ uint32_t Ap[2][4096];
    __shared__ uint32_t Bp[2][2048];
    const int tid = threadIdx.x, lane = tid & 31, wid = tid >> 5;
    const int g = lane >> 2, t4 = lane & 3;
    const int wm = (wid & 1) * 64, wn = (wid >> 1) * 16;
    const int m0 = blockIdx.y * 128, n0 = blockIdx.x * 64;
    const float* A = g_o;

    float acc[4][2][4] = {};
    float4 pa[4], pb[2];

#pragma unroll
    for (int i = 0; i < 4; i++) {
        int idx = tid + i * 256, r = idx >> 3, c4 = (idx & 7) * 4;
        pa[i] = *(const float4*)(A + (m0 + r) * DM + c4);
    }
#pragma unroll
    for (int i = 0; i < 2; i++) {
        int idx = tid + i * 256, r = idx >> 3, c4 = (idx & 7) * 4;
        pb[i] = *(const float4*)(B + (n0 + r) * DM + c4);
    }
#pragma unroll
    for (int i = 0; i < 4; i++) {
        int idx = tid + i * 256, r = idx >> 3, c4 = (idx & 7) * 4;
        uint4 u = {f2tf(pa[i].x), f2tf(pa[i].y), f2tf(pa[i].z), f2tf(pa[i].w)};
        sts_perm4(Ap[0], 4, r, c4, u);
    }
#pragma unroll
    for (int i = 0; i < 2; i++) {
        int idx = tid + i * 256, r = idx >> 3, c4 = (idx & 7) * 4;
        uint4 u = {f2tf(pb[i].x), f2tf(pb[i].y), f2tf(pb[i].z), f2tf(pb[i].w)};
        sts_perm4(Bp[0], 4, r, c4, u);
    }
    __syncthreads();

    for (int kt = 0; kt < DM / 32; kt++) {
        const int cur = kt & 1;
        if (kt + 1 < DM / 32) {
            int k0 = (kt + 1) * 32;
#pragma unroll
            for (int i = 0; i < 4; i++) {
                int idx = tid + i * 256, r = idx >> 3, c4 = (idx & 7) * 4;
                pa[i] = *(const float4*)(A + (m0 + r) * DM + k0 + c4);
            }
#pragma unroll
            for (int i = 0; i < 2; i++) {
                int idx = tid + i * 256, r = idx >> 3, c4 = (idx & 7) * 4;
                pb[i] = *(const float4*)(B + (n0 + r) * DM + k0 + c4);
            }
        }
#pragma unroll
        for (int s = 0; s < 4; s++) {
            uint4 av[4];
#pragma unroll
            for (int mi = 0; mi < 4; mi++)
                av[mi] = *(const uint4*)&Ap[cur][frag_addr(4, (wm >> 4) + mi, s, g, t4)];
            uint4 bv = *(const uint4*)&Bp[cur][frag_addr(4, wn >> 4, s, g, t4)];
#pragma unroll
            for (int mi = 0; mi < 4; mi++) {
                mma8(acc[mi][0], av[mi].x, av[mi].y, av[mi].z, av[mi].w, bv.x, bv.z);
                mma8(acc[mi][1], av[mi].x, av[mi].y, av[mi].z, av[mi].w, bv.y, bv.w);
            }
        }
        if (kt + 1 < DM / 32) {
#pragma unroll
            for (int i = 0; i < 4; i++) {
                int idx = tid + i * 256, r = idx >> 3, c4 = (idx & 7) * 4;
                uint4 u = {f2tf(pa[i].x), f2tf(pa[i].y), f2tf(pa[i].z), f2tf(pa[i].w)};
                sts_perm4(Ap[cur ^ 1], 4, r, c4, u);
            }
#pragma unroll
            for (int i = 0; i < 2; i++) {
                int idx = tid + i * 256, r = idx >> 3, c4 = (idx & 7) * 4;
                uint4 u = {f2tf(pb[i].x), f2tf(pb[i].y), f2tf(pb[i].z), f2tf(pb[i].w)};
                sts_perm4(Bp[cur ^ 1], 4, r, c4, u);
            }
        }
        __syncthreads();
    }

#pragma unroll
    for (int mi = 0; mi < 4; mi++)
#pragma unroll
        for (int ni = 0; ni < 2; ni++)
#pragma unroll
            for (int e = 0; e < 4; e++) {
                int row = m0 + wm + mi * 16 + g + (e >> 1) * 8;
                int col = n0 + wn + ni * 8 + t4 * 2 + (e & 1);
                C[row * DM + col] = acc[mi][ni][e];
            }
}

// ---------------------------------------------------------------------------
// Fused attention + exp + row-sum. Per (head, 128-row block), per 64-col tile:
//   S = (QK^T)/8 masked; attn <- exp(S) (unnormalized); Sp <- tf32(S);
//   O += S@V; rsum += exp(S). After the loop: deterministic row-sum reduction
//   (shfl over t4, per-n-warp-group smem slots reusing Vp) -> g_rsum.
// ---------------------------------------------------------------------------
__global__ __launch_bounds__(256, 2) void fused_attn(const int* __restrict__ mask,
                                                     float* __restrict__ attn) {
    extern __shared__ uint32_t sm[];
    uint32_t* Qp = sm;            // 8192 w
    uint32_t* Kp = sm + 8192;     // 2 x 4096 w
    uint32_t* Vp = sm + 16384;    // 4096 w (reused as rs[4][128] after loop)
    uint32_t* Sp = sm + 20480;    // 8192 w

    const int tid = threadIdx.x, lane = tid & 31, wid = tid >> 5;
    const int g = lane >> 2, t4 = lane & 3;
    const int wm = (wid & 1) * 64, wn = (wid >> 1) * 16;
    const int h = blockIdx.y, mt = blockIdx.x;
    const int m0 = mt * 128;
    const size_t attn_base = (size_t)h * SQ * SQ;
    const uint32_t* kg = g_kp + h * 32 * 4096;
    const uint32_t* vg = g_vp + h * 32 * 4096;

    // prologue: start K[0], stage Q (linear copy, already permuted+tf32)
#pragma unroll
    for (int i = 0; i < 4; i++)
        cpa16(Kp + tid * 4 + i * 1024, kg + tid * 4 + i * 1024);
    CPA_COMMIT;
    {
        const uint32_t* qg = g_qp + (h * 16 + mt) * 8192;
#pragma unroll
        for (int i = 0; i < 8; i++) {
            uint4 u = *(const uint4*)(qg + tid * 4 + i * 1024);
            *(uint4*)(Qp + tid * 4 + i * 1024) = u;
        }
    }

    float oacc[4][2][4] = {};
    float rsum[4][2] = {};

    for (int tt = 0; tt < NT; tt++) {
        const int t0 = tt * 64;
        uint32_t* Kc = Kp + (tt & 1) * 4096;

        CPA_WAIT(0);      // K[tt] landed
        __syncthreads();  // K visible; AV[tt-1] reads of Vp/Sp done

        // overlap V[tt] under S MMA; prefetch K[tt+1] under everything
#pragma unroll
        for (int i = 0; i < 4; i++)
            cpa16(Vp + tid * 4 + i * 1024, vg + tt * 4096 + tid * 4 + i * 1024);
        CPA_COMMIT;
        if (tt + 1 < NT) {
            uint32_t* Kn = Kp + ((tt + 1) & 1) * 4096;
#pragma unroll
            for (int i = 0; i < 4; i++)
                cpa16(Kn + tid * 4 + i * 1024, kg + (tt + 1) * 4096 + tid * 4 + i * 1024);
        }
        CPA_COMMIT;

        // S = Q K^T
        float sacc[4][2][4] = {};
#pragma unroll
        for (int s = 0; s < 8; s++) {
            uint4 aq[4];
#pragma unroll
            for (int mi = 0; mi < 4; mi++)
                aq[mi] = *(const uint4*)&Qp[frag_addr(8, (wm >> 4) + mi, s, g, t4)];
            uint4 bk = *(const uint4*)&Kc[frag_addr(8, wn >> 4, s, g, t4)];
#pragma unroll
            for (int mi = 0; mi < 4; mi++) {
                mma8(sacc[mi][0], aq[mi].x, aq[mi].y, aq[mi].z, aq[mi].w, bk.x, bk.z);
                mma8(sacc[mi][1], aq[mi].x, aq[mi].y, aq[mi].z, aq[mi].w, bk.y, bk.w);
            }
        }

        // epilogue: scale + mask; attn <- exp(v); Sp <- tf32(v); rsum += exp
#pragma unroll
        for (int mi = 0; mi < 4; mi++)
#pragma unroll
            for (int ni = 0; ni < 2; ni++)
#pragma unroll
                for (int e2 = 0; e2 < 2; e2++) {
                    int rl = wm + mi * 16 + g + e2 * 8;
                    int cl = wn + ni * 8 + t4 * 2;
                    int rg = m0 + rl, cg = t0 + cl;
                    int2 mk = *(const int2*)(mask + (size_t)rg * SQ + cg);
                    float v0 = sacc[mi][ni][e2 * 2] * 0.125f;
                    float v1 = sacc[mi][ni][e2 * 2 + 1] * 0.125f;
                    if (mk.x) v0 = -1e-7f;
                    if (mk.y) v1 = -1e-7f;
                    float e0 = __expf(v0), e1 = __expf(v1);
                    *(float2*)(attn + attn_base + (size_t)rg * SQ + cg) =
                        make_float2(e0, e1);
                    rsum[mi][e2] += e0 + e1;
                    Sp[perm_word(8, rl, cl)] = f2tf(v0);
                    Sp[perm_word(8, rl, cl + 1)] = f2tf(v1);
                }

        CPA_WAIT(1);      // V[tt] landed (K[tt+1] may still be in flight)
        __syncthreads();  // Vp + Sp visible

        // O += S @ V
#pragma unroll
        for (int s = 0; s < 8; s++) {
            uint4 as[4];
#pragma unroll
            for (int mi = 0; mi < 4; mi++)
                as[mi] = *(const uint4*)&Sp[frag_addr(8, (wm >> 4) + mi, s, g, t4)];
            uint4 bv = *(const uint4*)&Vp[frag_addr(8, wn >> 4, s, g, t4)];
#pragma unroll
            for (int mi = 0; mi < 4; mi++) {
                mma8(oacc[mi][0], as[mi].x, as[mi].y, as[mi].z, as[mi].w, bv.x, bv.z);
                mma8(oacc[mi][1], as[mi].x, as[mi].y, as[mi].z, as[mi].w, bv.y, bv.w);
            }
        }
    }

    // O epilogue
#pragma unroll
    for (int mi = 0; mi < 4; mi++)
#pragma unroll
        for (int ni = 0; ni < 2; ni++)
#pragma unroll
            for (int e = 0; e < 4; e++) {
                int row = m0 + wm + mi * 16 + g + (e >> 1) * 8;
                int col = wn + ni * 8 + t4 * 2 + (e & 1);
                g_o[row * DM + h * HD + col] = oacc[mi][ni][e];
            }

    // deterministic row-sum reduction: shfl over t4, then 4 n-warp-group slots
    __syncthreads();  // Vp reads done; reuse as rs[4][128]
    float* rs = (float*)Vp;
    rs[tid] = 0.f;
    rs[tid + 256] = 0.f;
    __syncthreads();
#pragma unroll
    for (int mi = 0; mi < 4; mi++)
#pragma unroll
        for (int e2 = 0; e2 < 2; e2++) {
            float r = rsum[mi][e2];
            r += __shfl_xor_sync(0xffffffffu, r, 1);
            r += __shfl_xor_sync(0xffffffffu, r, 2);
            if (t4 == 0) rs[(wid >> 1) * 128 + wm + mi * 16 + g + e2 * 8] = r;
        }
    __syncthreads();
    if (tid < 128)
        g_rsum[h * SQ + m0 + tid] =
            rs[tid] + rs[128 + tid] + rs[256 + tid] + rs[384 + tid];
}

// ---------------------------------------------------------------------------
// Scale pass: attn[row][:] *= 1/g_rsum[row]. Pure stream.
// ---------------------------------------------------------------------------
__global__ void scale_kernel(float* __restrict__ attn) {
    const size_t row = blockIdx.x;
    const float inv = 1.0f / g_rsum[row];
    const size_t base = row * SQ;
    const int tid = threadIdx.x;
    float4 a = *(const float4*)(attn + base + tid * 4);
    float4 b = *(const float4*)(attn + base + 1024 + tid * 4);
    a.x *= inv; a.y *= inv; a.z *= inv; a.w *= inv;
    b.x *= inv; b.y *= inv; b.z *= inv; b.w *= inv;
    *(float4*)(attn + base + tid * 4) = a;
    *(float4*)(attn + base + 1024 + tid * 4) = b;
}

extern "C" void kernel_launch(void* const* d_in, const int* in_sizes, int n_in,
                              void* d_out, int out_size) {
    const float* q_in = (const float*)d_in[0];
    const float* k_in = (const float*)d_in[1];
    const float* v_in = (const float*)d_in[2];
    const int* mask = (const int*)d_in[3];
    const float* Wq = (const float*)d_in[4];
    const float* Wk = (const float*)d_in[5];
    const float* Wv = (const float*)d_in[6];
    const float* Wo = (const float*)d_in[7];

    float* out = (float*)d_out;           // [S, DM]
    float* attn = out + (size_t)SQ * DM;  // [H, S, S]

    static int smem_set = 0;
    if (!smem_set) {
        cudaFuncSetAttribute(fused_attn, cudaFuncAttributeMaxDynamicSharedMemorySize,
                             114688);
        smem_set = 1;
    }

    dim3 gQKV(DM / 64, SQ / 128, 3);  // (16, 16, 3)
    gemm_qkv<<<gQKV, 256>>>(q_in, k_in, v_in, Wq, Wk, Wv);

    dim3 gFused(SQ / 128, NH, 1);  // (16, 16)
    fused_attn<<<gFused, 256, 114688>>>(mask, attn);

    scale_kernel<<<NH * SQ, 256>>>(attn);

    dim3 gOut(DM / 64, SQ / 128, 1);
    gemm_out<<<gOut, 256>>>(Wo, out);
}

// round 6
// speedup vs baseline: 1.0359x; 1.0359x over previous
#include <cuda_runtime.h>
#include <cstdint>

#define SQ 2048
#define DM 1024
#define NH 16
#define HD 64
#define NT (SQ / 64)  // 32 column tiles

// Scratch (allocation-free)
__device__ float g_o[SQ * DM];             // attention output O (fp32)
__device__ float g_rsum[NH * SQ];          // per-row softmax denominators
__device__ uint32_t g_mbits[64 * SQ];      // mask bitmask, [wordcol][row]
__device__ uint32_t g_qp[NH * 16 * 8192];  // Q, permuted frag layout per (h, mtile)
__device__ uint32_t g_kp[NH * 32 * 4096];  // K, permuted per (h, ttile)
__device__ uint32_t g_vp[NH * 32 * 4096];  // V^T, permuted per (h, ttile)

__device__ __forceinline__ uint32_t f2tf(float f) {
    uint32_t u;
    asm("cvt.rna.tf32.f32 %0, %1;" : "=r"(u) : "f"(f));
    return u;
}

__device__ __forceinline__ void mma8(float* c, uint32_t a0, uint32_t a1, uint32_t a2,
                                     uint32_t a3, uint32_t b0, uint32_t b1) {
    asm("mma.sync.aligned.m16n8k8.row.col.f32.tf32.tf32.f32 "
        "{%0,%1,%2,%3},{%4,%5,%6,%7},{%8,%9},{%0,%1,%2,%3};"
        : "+f"(c[0]), "+f"(c[1]), "+f"(c[2]), "+f"(c[3])
        : "r"(a0), "r"(a1), "r"(a2), "r"(a3), "r"(b0), "r"(b1));
}

// Permuted fragment-major smem/global layout (one LDS.128 per mma fragment).
__device__ __forceinline__ int perm_word(int NS, int r, int k) {
    int gg = r & 7;
    int kk = k & 7;
    int L = gg * 4 + ((kk & 3) ^ (gg & 3));
    return (((r >> 4) * NS + (k >> 3)) * 32 + L) * 4 + ((r >> 3) & 1) + 2 * (kk >> 2);
}
__device__ __forceinline__ void sts_perm4(uint32_t* S, int NS, int r, int c4, uint4 u) {
    int gg = r & 7;
    int base = (((r >> 4) * NS + (c4 >> 3)) * 32 + gg * 4) * 4 + ((r >> 3) & 1) +
               2 * ((c4 >> 2) & 1);
    int x = gg & 3;
    S[base + (0 ^ x) * 4] = u.x;
    S[base + (1 ^ x) * 4] = u.y;
    S[base + (2 ^ x) * 4] = u.z;
    S[base + (3 ^ x) * 4] = u.w;
}
__device__ __forceinline__ int frag_addr(int NS, int band, int s, int g, int t4) {
    return ((band * NS + s) * 32 + g * 4 + (t4 ^ (g & 3))) * 4;
}

__device__ __forceinline__ void cpa16(void* dst, const void* src) {
    uint32_t s = (uint32_t)__cvta_generic_to_shared(dst);
    asm volatile("cp.async.cg.shared.global [%0], [%1], 16;" ::"r"(s), "l"(src));
}
#define CPA_COMMIT asm volatile("cp.async.commit_group;")
#define CPA_WAIT(n) asm volatile("cp.async.wait_group %0;" ::"n"(n))

// ---------------------------------------------------------------------------
// Kernel A: QKV projections (z=0..2) + mask bit-compaction (z=3, overlapped).
// Projections: C = A @ W^T, tf32-rounded, stored in permuted fragment layout.
// ---------------------------------------------------------------------------
__global__ __launch_bounds__(256) void gemm_qkv(
    const float* __restrict__ q_in, const float* __restrict__ k_in,
    const float* __restrict__ v_in, const float* __restrict__ Wq,
    const float* __restrict__ Wk, const float* __restrict__ Wv,
    const int* __restrict__ mask) {
    const int z = blockIdx.z;
    const int tid = threadIdx.x, lane = tid & 31, wid = tid >> 5;

    if (z == 3) {
        // mask compaction: one warp per row; thread t handles cols t*64..t*64+63.
        const int bid = blockIdx.y * 16 + blockIdx.x;
        const int row = bid * 8 + wid;
        const int4* mp = (const int4*)(mask + (size_t)row * SQ + lane * 64);
        uint32_t w0 = 0, w1 = 0;
#pragma unroll
        for (int i = 0; i < 16; i++) {
            int4 m = mp[i];
            uint32_t bits = (m.x != 0 ? 1u : 0u) | (m.y != 0 ? 2u : 0u) |
                            (m.z != 0 ? 4u : 0u) | (m.w != 0 ? 8u : 0u);
            if (i < 8)
                w0 |= bits << (i * 4);
            else
                w1 |= bits << ((i - 8) * 4);
        }
        g_mbits[(lane * 2 + 0) * SQ + row] = w0;
        g_mbits[(lane * 2 + 1) * SQ + row] = w1;
        return;
    }

    const float* A = z == 0 ? q_in : z == 1 ? k_in : v_in;
    const float* B = z == 0 ? Wq : z == 1 ? Wk : Wv;
    uint32_t* D = z == 0 ? g_qp : z == 1 ? g_kp : g_vp;

    __shared__ uint32_t Ap[2][4096];  // 128 x 32 each
    __shared__ uint32_t Bp[2][2048];  // 64 x 32 each
    const int g = lane >> 2, t4 = lane & 3;
    const int wm = (wid & 1) * 64, wn = (wid >> 1) * 16;
    const int m0 = blockIdx.y * 128, n0 = blockIdx.x * 64;

    float acc[4][2][4] = {};
    float4 pa[4], pb[2];

#pragma unroll
    for (int i = 0; i < 4; i++) {
        int idx = tid + i * 256, r = idx >> 3, c4 = (idx & 7) * 4;
        pa[i] = *(const float4*)(A + (m0 + r) * DM + c4);
    }
#pragma unroll
    for (int i = 0; i < 2; i++) {
        int idx = tid + i * 256, r = idx >> 3, c4 = (idx & 7) * 4;
        pb[i] = *(const float4*)(B + (n0 + r) * DM + c4);
    }
#pragma unroll
    for (int i = 0; i < 4; i++) {
        int idx = tid + i * 256, r = idx >> 3, c4 = (idx & 7) * 4;
        uint4 u = {f2tf(pa[i].x), f2tf(pa[i].y), f2tf(pa[i].z), f2tf(pa[i].w)};
        sts_perm4(Ap[0], 4, r, c4, u);
    }
#pragma unroll
    for (int i = 0; i < 2; i++) {
        int idx = tid + i * 256, r = idx >> 3, c4 = (idx & 7) * 4;
        uint4 u = {f2tf(pb[i].x), f2tf(pb[i].y), f2tf(pb[i].z), f2tf(pb[i].w)};
        sts_perm4(Bp[0], 4, r, c4, u);
    }
    __syncthreads();

    for (int kt = 0; kt < DM / 32; kt++) {
        const int cur = kt & 1;
        if (kt + 1 < DM / 32) {
            int k0 = (kt + 1) * 32;
#pragma unroll
            for (int i = 0; i < 4; i++) {
                int idx = tid + i * 256, r = idx >> 3, c4 = (idx & 7) * 4;
                pa[i] = *(const float4*)(A + (m0 + r) * DM + k0 + c4);
            }
#pragma unroll
            for (int i = 0; i < 2; i++) {
                int idx = tid + i * 256, r = idx >> 3, c4 = (idx & 7) * 4;
                pb[i] = *(const float4*)(B + (n0 + r) * DM + k0 + c4);
            }
        }
#pragma unroll
        for (int s = 0; s < 4; s++) {
            uint4 av[4];
#pragma unroll
            for (int mi = 0; mi < 4; mi++)
                av[mi] = *(const uint4*)&Ap[cur][frag_addr(4, (wm >> 4) + mi, s, g, t4)];
            uint4 bv = *(const uint4*)&Bp[cur][frag_addr(4, wn >> 4, s, g, t4)];
#pragma unroll
            for (int mi = 0; mi < 4; mi++) {
                mma8(acc[mi][0], av[mi].x, av[mi].y, av[mi].z, av[mi].w, bv.x, bv.z);
                mma8(acc[mi][1], av[mi].x, av[mi].y, av[mi].z, av[mi].w, bv.y, bv.w);
            }
        }
        if (kt + 1 < DM / 32) {
#pragma unroll
            for (int i = 0; i < 4; i++) {
                int idx = tid + i * 256, r = idx >> 3, c4 = (idx & 7) * 4;
                uint4 u = {f2tf(pa[i].x), f2tf(pa[i].y), f2tf(pa[i].z), f2tf(pa[i].w)};
                sts_perm4(Ap[cur ^ 1], 4, r, c4, u);
            }
#pragma unroll
            for (int i = 0; i < 2; i++) {
                int idx = tid + i * 256, r = idx >> 3, c4 = (idx & 7) * 4;
                uint4 u = {f2tf(pb[i].x), f2tf(pb[i].y), f2tf(pb[i].z), f2tf(pb[i].w)};
                sts_perm4(Bp[cur ^ 1], 4, r, c4, u);
            }
        }
        __syncthreads();
    }

    const int h = blockIdx.x, by = blockIdx.y;
#pragma unroll
    for (int mi = 0; mi < 4; mi++)
#pragma unroll
        for (int ni = 0; ni < 2; ni++)
#pragma unroll
            for (int e = 0; e < 4; e++) {
                int row = wm + mi * 16 + g + ((e >> 1) * 8);  // 0..127 (m rel)
                int col = wn + ni * 8 + t4 * 2 + (e & 1);     // 0..63  (d rel)
                uint32_t val = f2tf(acc[mi][ni][e]);
                int idx;
                if (z == 0) {
                    idx = (h * 16 + by) * 8192 + perm_word(8, row, col);
                } else {
                    int tile = by * 2 + (row >> 6);
                    int r64 = row & 63;
                    idx = (h * 32 + tile) * 4096 +
                          (z == 1 ? perm_word(8, r64, col) : perm_word(8, col, r64));
                }
                D[idx] = val;
            }
}

// ---------------------------------------------------------------------------
// Fused attention + exp + row-sum. Mask comes from the L2-resident bitmask
// (8 broadcast LDG.32 per tile, issued at tile top, consumed in epilogue).
// ---------------------------------------------------------------------------
__global__ __launch_bounds__(256, 2) void fused_attn(float* __restrict__ attn) {
    extern __shared__ uint32_t sm[];
    uint32_t* Qp = sm;            // 8192 w
    uint32_t* Kp = sm + 8192;     // 2 x 4096 w
    uint32_t* Vp = sm + 16384;    // 4096 w (reused as rs[4][128] after loop)
    uint32_t* Sp = sm + 20480;    // 8192 w

    const int tid = threadIdx.x, lane = tid & 31, wid = tid >> 5;
    const int g = lane >> 2, t4 = lane & 3;
    const int wm = (wid & 1) * 64, wn = (wid >> 1) * 16;
    const int h = blockIdx.y, mt = blockIdx.x;
    const int m0 = mt * 128;
    const int slot = wn >> 5;  // which 32-col word this warp's columns fall in
    const size_t attn_base = (size_t)h * SQ * SQ;
    const uint32_t* kg = g_kp + h * 32 * 4096;
    const uint32_t* vg = g_vp + h * 32 * 4096;

    // prologue: start K[0], stage Q (linear copy, already permuted+tf32)
#pragma unroll
    for (int i = 0; i < 4; i++)
        cpa16(Kp + tid * 4 + i * 1024, kg + tid * 4 + i * 1024);
    CPA_COMMIT;
    {
        const uint32_t* qg = g_qp + (h * 16 + mt) * 8192;
#pragma unroll
        for (int i = 0; i < 8; i++) {
            uint4 u = *(const uint4*)(qg + tid * 4 + i * 1024);
            *(uint4*)(Qp + tid * 4 + i * 1024) = u;
        }
    }

    float oacc[4][2][4] = {};
    float rsum[4][2] = {};

    for (int tt = 0; tt < NT; tt++) {
        const int t0 = tt * 64;
        uint32_t* Kc = Kp + (tt & 1) * 4096;

        CPA_WAIT(0);      // K[tt] landed
        __syncthreads();  // K visible; AV[tt-1] reads of Vp/Sp done

        // mask bits for this tile (L2 hits, latency hidden under S MMA)
        uint32_t mw[4][2];
        {
            const uint32_t* mb = g_mbits + (tt * 2 + slot) * SQ + m0;
#pragma unroll
            for (int mi = 0; mi < 4; mi++)
#pragma unroll
                for (int e2 = 0; e2 < 2; e2++)
                    mw[mi][e2] = mb[wm + mi * 16 + g + e2 * 8];
        }

        // overlap V[tt] under S MMA; prefetch K[tt+1] under everything
#pragma unroll
        for (int i = 0; i < 4; i++)
            cpa16(Vp + tid * 4 + i * 1024, vg + tt * 4096 + tid * 4 + i * 1024);
        CPA_COMMIT;
        if (tt + 1 < NT) {
            uint32_t* Kn = Kp + ((tt + 1) & 1) * 4096;
#pragma unroll
            for (int i = 0; i < 4; i++)
                cpa16(Kn + tid * 4 + i * 1024, kg + (tt + 1) * 4096 + tid * 4 + i * 1024);
        }
        CPA_COMMIT;

        // S = Q K^T
        float sacc[4][2][4] = {};
#pragma unroll
        for (int s = 0; s < 8; s++) {
            uint4 aq[4];
#pragma unroll
            for (int mi = 0; mi < 4; mi++)
                aq[mi] = *(const uint4*)&Qp[frag_addr(8, (wm >> 4) + mi, s, g, t4)];
            uint4 bk = *(const uint4*)&Kc[frag_addr(8, wn >> 4, s, g, t4)];
#pragma unroll
            for (int mi = 0; mi < 4; mi++) {
                mma8(sacc[mi][0], aq[mi].x, aq[mi].y, aq[mi].z, aq[mi].w, bk.x, bk.z);
                mma8(sacc[mi][1], aq[mi].x, aq[mi].y, aq[mi].z, aq[mi].w, bk.y, bk.w);
            }
        }

        // epilogue: scale + mask; attn <- exp(v) (streaming); Sp <- tf32(v)
#pragma unroll
        for (int mi = 0; mi < 4; mi++)
#pragma unroll
            for (int ni = 0; ni < 2; ni++)
#pragma unroll
                for (int e2 = 0; e2 < 2; e2++) {
                    int rl = wm + mi * 16 + g + e2 * 8;
                    int cl = wn + ni * 8 + t4 * 2;
                    int rg = m0 + rl, cg = t0 + cl;
                    float v0 = sacc[mi][ni][e2 * 2] * 0.125f;
                    float v1 = sacc[mi][ni][e2 * 2 + 1] * 0.125f;
                    uint32_t w = mw[mi][e2];
                    if ((w >> (cl & 31)) & 1) v0 = -1e-7f;
                    if ((w >> ((cl & 31) + 1)) & 1) v1 = -1e-7f;
                    float e0 = __expf(v0), e1 = __expf(v1);
                    __stcs((float2*)(attn + attn_base + (size_t)rg * SQ + cg),
                           make_float2(e0, e1));
                    rsum[mi][e2] += e0 + e1;
                    Sp[perm_word(8, rl, cl)] = f2tf(v0);
                    Sp[perm_word(8, rl, cl + 1)] = f2tf(v1);
                }

        CPA_WAIT(1);      // V[tt] landed (K[tt+1] may still be in flight)
        __syncthreads();  // Vp + Sp visible

        // O += S @ V
#pragma unroll
        for (int s = 0; s < 8; s++) {
            uint4 as[4];
#pragma unroll
            for (int mi = 0; mi < 4; mi++)
                as[mi] = *(const uint4*)&Sp[frag_addr(8, (wm >> 4) + mi, s, g, t4)];
            uint4 bv = *(const uint4*)&Vp[frag_addr(8, wn >> 4, s, g, t4)];
#pragma unroll
            for (int mi = 0; mi < 4; mi++) {
                mma8(oacc[mi][0], as[mi].x, as[mi].y, as[mi].z, as[mi].w, bv.x, bv.z);
                mma8(oacc[mi][1], as[mi].x, as[mi].y, as[mi].z, as[mi].w, bv.y, bv.w);
            }
        }
    }

    // O epilogue
#pragma unroll
    for (int mi = 0; mi < 4; mi++)
#pragma unroll
        for (int ni = 0; ni < 2; ni++)
#pragma unroll
            for (int e = 0; e < 4; e++) {
                int row = m0 + wm + mi * 16 + g + (e >> 1) * 8;
                int col = wn + ni * 8 + t4 * 2 + (e & 1);
                g_o[row * DM + h * HD + col] = oacc[mi][ni][e];
            }

    // deterministic row-sum reduction: shfl over t4, then 4 n-warp-group slots
    __syncthreads();  // Vp reads done; reuse as rs[4][128]
    float* rs = (float*)Vp;
    rs[tid] = 0.f;
    rs[tid + 256] = 0.f;
    __syncthreads();
#pragma unroll
    for (int mi = 0; mi < 4; mi++)
#pragma unroll
        for (int e2 = 0; e2 < 2; e2++) {
            float r = rsum[mi][e2];
            r += __shfl_xor_sync(0xffffffffu, r, 1);
            r += __shfl_xor_sync(0xffffffffu, r, 2);
            if (t4 == 0) rs[(wid >> 1) * 128 + wm + mi * 16 + g + e2 * 8] = r;
        }
    __syncthreads();
    if (tid < 128)
        g_rsum[h * SQ + m0 + tid] =
            rs[tid] + rs[128 + tid] + rs[256 + tid] + rs[384 + tid];
}

// ---------------------------------------------------------------------------
// Kernel C (heterogeneous): blocks 0..511 = output projection (BM=64, BN=64);
// blocks 512+ = attn scale stream (16 rows each). Overlaps latency-bound GEMM
// with the bandwidth-bound scale.
// ---------------------------------------------------------------------------
__global__ __launch_bounds__(256) void out_scale(const float* __restrict__ B,
                                                 float* __restrict__ C,
                                                 float* __restrict__ attn) {
    const int bid = blockIdx.x;
    const int tid = threadIdx.x;

    if (bid >= 512) {
        // scale: 2048 blocks x 16 rows
        const int r0 = (bid - 512) * 16;
#pragma unroll 2
        for (int r = 0; r < 16; r++) {
            const int row = r0 + r;
            const float inv = 1.0f / g_rsum[row];
            float* p = attn + (size_t)row * SQ;
            float4 a = __ldcs((const float4*)(p + tid * 4));
            float4 b = __ldcs((const float4*)(p + 1024 + tid * 4));
            a.x *= inv; a.y *= inv; a.z *= inv; a.w *= inv;
            b.x *= inv; b.y *= inv; b.z *= inv; b.w *= inv;
            __stcs((float4*)(p + tid * 4), a);
            __stcs((float4*)(p + 1024 + tid * 4), b);
        }
        return;
    }

    // output projection: C = g_o @ B^T, BM=64, BN=64, BK=32, double-buffered
    __shared__ uint32_t Ap[2][2048];
    __shared__ uint32_t Bp[2][2048];
    const int lane = tid & 31, wid = tid >> 5;
    const int g = lane >> 2, t4 = lane & 3;
    const int wm = (wid & 1) * 32, wn = (wid >> 1) * 16;
    const int m0 = (bid >> 4) * 64, n0 = (bid & 15) * 64;
    const float* A = g_o;

    float acc[2][2][4] = {};
    float4 pa[2], pb[2];

#pragma unroll
    for (int i = 0; i < 2; i++) {
        int idx = tid + i * 256, r = idx >> 3, c4 = (idx & 7) * 4;
        pa[i] = *(const float4*)(A + (m0 + r) * DM + c4);
        pb[i] = *(const float4*)(B + (n0 + r) * DM + c4);
    }
#pragma unroll
    for (int i = 0; i < 2; i++) {
        int idx = tid + i * 256, r = idx >> 3, c4 = (idx & 7) * 4;
        uint4 ua = {f2tf(pa[i].x), f2tf(pa[i].y), f2tf(pa[i].z), f2tf(pa[i].w)};
        sts_perm4(Ap[0], 4, r, c4, ua);
        uint4 ub = {f2tf(pb[i].x), f2tf(pb[i].y), f2tf(pb[i].z), f2tf(pb[i].w)};
        sts_perm4(Bp[0], 4, r, c4, ub);
    }
    __syncthreads();

    for (int kt = 0; kt < DM / 32; kt++) {
        const int cur = kt & 1;
        if (kt + 1 < DM / 32) {
            int k0 = (kt + 1) * 32;
#pragma unroll
            for (int i = 0; i < 2; i++) {
                int idx = tid + i * 256, r = idx >> 3, c4 = (idx & 7) * 4;
                pa[i] = *(const float4*)(A + (m0 + r) * DM + k0 + c4);
                pb[i] = *(const float4*)(B + (n0 + r) * DM + k0 + c4);
            }
        }
#pragma unroll
        for (int s = 0; s < 4; s++) {
            uint4 av[2];
#pragma unroll
            for (int mi = 0; mi < 2; mi++)
                av[mi] = *(const uint4*)&Ap[cur][frag_addr(4, (wm >> 4) + mi, s, g, t4)];
            uint4 bv = *(const uint4*)&Bp[cur][frag_addr(4, wn >> 4, s, g, t4)];
#pragma unroll
            for (int mi = 0; mi < 2; mi++) {
                mma8(acc[mi][0], av[mi].x, av[mi].y, av[mi].z, av[mi].w, bv.x, bv.z);
                mma8(acc[mi][1], av[mi].x, av[mi].y, av[mi].z, av[mi].w, bv.y, bv.w);
            }
        }
        if (kt + 1 < DM / 32) {
#pragma unroll
            for (int i = 0; i < 2; i++) {
                int idx = tid + i * 256, r = idx >> 3, c4 = (idx & 7) * 4;
                uint4 ua = {f2tf(pa[i].x), f2tf(pa[i].y), f2tf(pa[i].z), f2tf(pa[i].w)};
                sts_perm4(Ap[cur ^ 1], 4, r, c4, ua);
                uint4 ub = {f2tf(pb[i].x), f2tf(pb[i].y), f2tf(pb[i].z), f2tf(pb[i].w)};
                sts_perm4(Bp[cur ^ 1], 4, r, c4, ub);
            }
        }
        __syncthreads();
    }

#pragma unroll
    for (int mi = 0; mi < 2; mi++)
#pragma unroll
        for (int ni = 0; ni < 2; ni++)
#pragma unroll
            for (int e = 0; e < 4; e++) {
                int row = m0 + wm + mi * 16 + g + (e >> 1) * 8;
                int col = n0 + wn + ni * 8 + t4 * 2 + (e & 1);
                C[row * DM + col] = acc[mi][ni][e];
            }
}

extern "C" void kernel_launch(void* const* d_in, const int* in_sizes, int n_in,
                              void* d_out, int out_size) {
    const float* q_in = (const float*)d_in[0];
    const float* k_in = (const float*)d_in[1];
    const float* v_in = (const float*)d_in[2];
    const int* mask = (const int*)d_in[3];
    const float* Wq = (const float*)d_in[4];
    const float* Wk = (const float*)d_in[5];
    const float* Wv = (const float*)d_in[6];
    const float* Wo = (const float*)d_in[7];

    float* out = (float*)d_out;           // [S, DM]
    float* attn = out + (size_t)SQ * DM;  // [H, S, S]

    static int smem_set = 0;
    if (!smem_set) {
        cudaFuncSetAttribute(fused_attn, cudaFuncAttributeMaxDynamicSharedMemorySize,
                             114688);
        smem_set = 1;
    }

    dim3 gQKV(DM / 64, SQ / 128, 4);  // z=0..2 projections, z=3 mask compaction
    gemm_qkv<<<gQKV, 256>>>(q_in, k_in, v_in, Wq, Wk, Wv, mask);

    dim3 gFused(SQ / 128, NH, 1);  // (16, 16)
    fused_attn<<<gFused, 256, 114688>>>(attn);

    out_scale<<<512 + 2048, 256>>>(Wo, out, attn);
}

// round 7
// speedup vs baseline: 1.2872x; 1.2425x over previous
#include <cuda_runtime.h>
#include <cstdint>

#define SQ 2048
#define DM 1024
#define NH 16
#define HD 64
#define NT (SQ / 64)  // 32 column tiles in fused

// Scratch (allocation-free)
__device__ float g_rsum[NH * SQ];            // per-row softmax denominators
__device__ uint32_t g_mbits[64 * SQ];        // mask bitmask, [wordcol][row]
__device__ uint32_t g_ap[3 * 512 * 4096];    // q,k,v inputs: permuted [z][mt][kt] tiles
__device__ uint32_t g_wp[4 * 256 * 4096];    // Wq,Wk,Wv,Wo: permuted [w][nt][kt] tiles
__device__ uint32_t g_op[512 * 4096];        // attention out O: permuted [mt][kt] tiles
__device__ uint32_t g_qp[NH * 16 * 8192];    // Q proj, permuted per (h, mtile)
__device__ uint32_t g_kp[NH * 32 * 4096];    // K proj, permuted per (h, ttile)
__device__ uint32_t g_vp[NH * 32 * 4096];    // V^T proj, permuted per (h, ttile)

__device__ __forceinline__ uint32_t f2tf(float f) {
    uint32_t u;
    asm("cvt.rna.tf32.f32 %0, %1;" : "=r"(u) : "f"(f));
    return u;
}

__device__ __forceinline__ void mma8(float* c, uint32_t a0, uint32_t a1, uint32_t a2,
                                     uint32_t a3, uint32_t b0, uint32_t b1) {
    asm("mma.sync.aligned.m16n8k8.row.col.f32.tf32.tf32.f32 "
        "{%0,%1,%2,%3},{%4,%5,%6,%7},{%8,%9},{%0,%1,%2,%3};"
        : "+f"(c[0]), "+f"(c[1]), "+f"(c[2]), "+f"(c[3])
        : "r"(a0), "r"(a1), "r"(a2), "r"(a3), "r"(b0), "r"(b1));
}

// Permuted fragment-major layout (one LDS.128 per mma fragment).
__device__ __forceinline__ int perm_word(int NS, int r, int k) {
    int gg = r & 7;
    int kk = k & 7;
    int L = gg * 4 + ((kk & 3) ^ (gg & 3));
    return (((r >> 4) * NS + (k >> 3)) * 32 + L) * 4 + ((r >> 3) & 1) + 2 * (kk >> 2);
}
__device__ __forceinline__ void sts_perm4(uint32_t* S, int NS, int r, int c4, uint4 u) {
    int gg = r & 7;
    int base = (((r >> 4) * NS + (c4 >> 3)) * 32 + gg * 4) * 4 + ((r >> 3) & 1) +
               2 * ((c4 >> 2) & 1);
    int x = gg & 3;
    S[base + (0 ^ x) * 4] = u.x;
    S[base + (1 ^ x) * 4] = u.y;
    S[base + (2 ^ x) * 4] = u.z;
    S[base + (3 ^ x) * 4] = u.w;
}
__device__ __forceinline__ int frag_addr(int NS, int band, int s, int g, int t4) {
    return ((band * NS + s) * 32 + g * 4 + (t4 ^ (g & 3))) * 4;
}

__device__ __forceinline__ void cpa16(void* dst, const void* src) {
    uint32_t s = (uint32_t)__cvta_generic_to_shared(dst);
    asm volatile("cp.async.cg.shared.global [%0], [%1], 16;" ::"r"(s), "l"(src));
}
#define CPA_COMMIT asm volatile("cp.async.commit_group;")
#define CPA_WAIT(n) asm volatile("cp.async.wait_group %0;" ::"n"(n))

// ---------------------------------------------------------------------------
// Pre-pass: tf32-round + pre-permute activations (blocks 0..1535) and weights
// (1536..2559) into fragment-major global tiles; mask bit-compaction (2560+).
// Pure bandwidth; smem bounce keeps global writes coalesced.
// ---------------------------------------------------------------------------
__global__ __launch_bounds__(256) void prep(
    const float* __restrict__ q_in, const float* __restrict__ k_in,
    const float* __restrict__ v_in, const float* __restrict__ Wq,
    const float* __restrict__ Wk, const float* __restrict__ Wv,
    const float* __restrict__ Wo, const int* __restrict__ mask) {
    const int bid = blockIdx.x;
    const int tid = threadIdx.x;

    if (bid >= 2560) {  // mask compaction: 256 blocks x 8 rows (warp per row)
        const int lane = tid & 31, wid = tid >> 5;
        const int row = (bid - 2560) * 8 + wid;
        const int4* mp = (const int4*)(mask + (size_t)row * SQ + lane * 64);
        uint32_t w0 = 0, w1 = 0;
#pragma unroll
        for (int i = 0; i < 16; i++) {
            int4 m = mp[i];
            uint32_t bits = (m.x != 0 ? 1u : 0u) | (m.y != 0 ? 2u : 0u) |
                            (m.z != 0 ? 4u : 0u) | (m.w != 0 ? 8u : 0u);
            if (i < 8)
                w0 |= bits << (i * 4);
            else
                w1 |= bits << ((i - 8) * 4);
        }
        g_mbits[(lane * 2 + 0) * SQ + row] = w0;
        g_mbits[(lane * 2 + 1) * SQ + row] = w1;
        return;
    }

    __shared__ uint32_t sp[4096];
    const float* src;
    uint32_t* dst;
    int r0, c0;
    if (bid < 1536) {  // activation tile: z, mt(16), kt(32)
        int z = bid >> 9, rem = bid & 511;
        src = z == 0 ? q_in : z == 1 ? k_in : v_in;
        r0 = (rem >> 5) * 128;
        c0 = (rem & 31) * 32;
        dst = g_ap + bid * 4096;
    } else {  // weight tile: w(4), nt(8), kt(32)
        int wb = bid - 1536;
        int w = wb >> 8, rem = wb & 255;
        src = w == 0 ? Wq : w == 1 ? Wk : w == 2 ? Wv : Wo;
        r0 = (rem >> 5) * 128;
        c0 = (rem & 31) * 32;
        dst = g_wp + wb * 4096;
    }
#pragma unroll
    for (int i = 0; i < 4; i++) {
        int idx = tid + i * 256, r = idx >> 3, c4 = (idx & 7) * 4;
        float4 v = *(const float4*)(src + (size_t)(r0 + r) * DM + c0 + c4);
        uint4 u = {f2tf(v.x), f2tf(v.y), f2tf(v.z), f2tf(v.w)};
        sts_perm4(sp, 4, r, c4, u);
    }
    __syncthreads();
#pragma unroll
    for (int i = 0; i < 4; i++)
        *(uint4*)(dst + tid * 4 + i * 1024) = *(const uint4*)(sp + tid * 4 + i * 1024);
}

// ---------------------------------------------------------------------------
// QKV projection GEMMs from pre-permuted tiles. BM=128, BN=128, BK=32,
// cp.async double-buffered, 1 sync per k-tile, zero in-loop conversion.
// Epilogue writes per-head permuted layouts for the fused kernel.
// ---------------------------------------------------------------------------
__global__ __launch_bounds__(256, 2) void gemm_qkv() {
    extern __shared__ uint32_t sm[];  // 2 stages x (A 4096 | B 4096)
    const int z = blockIdx.z, mt = blockIdx.y, nt = blockIdx.x;
    const int tid = threadIdx.x, lane = tid & 31, wid = tid >> 5;
    const int g = lane >> 2, t4 = lane & 3;
    const int wm = (wid & 1) * 64, wn = (wid >> 1) * 32;
    const uint32_t* At = g_ap + (size_t)(z * 512 + mt * 32) * 4096;
    const uint32_t* Bt = g_wp + (size_t)(z * 256 + nt * 32) * 4096;

#pragma unroll
    for (int i = 0; i < 4; i++) {
        cpa16(sm + tid * 4 + i * 1024, At + tid * 4 + i * 1024);
        cpa16(sm + 4096 + tid * 4 + i * 1024, Bt + tid * 4 + i * 1024);
    }
    CPA_COMMIT;

    float acc[4][4][4] = {};

    for (int kt = 0; kt < 32; kt++) {
        uint32_t* S = sm + (kt & 1) * 8192;
        CPA_WAIT(0);
        __syncthreads();
        if (kt + 1 < 32) {
            uint32_t* Nx = sm + ((kt + 1) & 1) * 8192;
            const uint32_t* An = At + (kt + 1) * 4096;
            const uint32_t* Bn = Bt + (kt + 1) * 4096;
#pragma unroll
            for (int i = 0; i < 4; i++) {
                cpa16(Nx + tid * 4 + i * 1024, An + tid * 4 + i * 1024);
                cpa16(Nx + 4096 + tid * 4 + i * 1024, Bn + tid * 4 + i * 1024);
            }
            CPA_COMMIT;
        }
#pragma unroll
        for (int s = 0; s < 4; s++) {
            uint4 av[4], bv[2];
#pragma unroll
            for (int mi = 0; mi < 4; mi++)
                av[mi] = *(const uint4*)&S[frag_addr(4, (wm >> 4) + mi, s, g, t4)];
#pragma unroll
            for (int bi = 0; bi < 2; bi++)
                bv[bi] = *(const uint4*)&S[4096 + frag_addr(4, (wn >> 4) + bi, s, g, t4)];
#pragma unroll
            for (int mi = 0; mi < 4; mi++)
#pragma unroll
                for (int bi = 0; bi < 2; bi++) {
                    mma8(acc[mi][bi * 2], av[mi].x, av[mi].y, av[mi].z, av[mi].w,
                         bv[bi].x, bv[bi].z);
                    mma8(acc[mi][bi * 2 + 1], av[mi].x, av[mi].y, av[mi].z, av[mi].w,
                         bv[bi].y, bv[bi].w);
                }
        }
    }

    // epilogue: tf32-round, write per-head permuted layouts
#pragma unroll
    for (int mi = 0; mi < 4; mi++)
#pragma unroll
        for (int ni = 0; ni < 4; ni++)
#pragma unroll
            for (int e = 0; e < 4; e++) {
                int row = wm + mi * 16 + g + ((e >> 1) * 8);  // 0..127
                int col = wn + ni * 8 + t4 * 2 + (e & 1);     // 0..127
                int gn = nt * 128 + col;
                int h = gn >> 6, c64 = gn & 63;
                uint32_t val = f2tf(acc[mi][ni][e]);
                if (z == 0) {
                    g_qp[(h * 16 + mt) * 8192 + perm_word(8, row, c64)] = val;
                } else {
                    int tile = mt * 2 + (row >> 6);
                    int r64 = row & 63;
                    if (z == 1)
                        g_kp[(h * 32 + tile) * 4096 + perm_word(8, r64, c64)] = val;
                    else
                        g_vp[(h * 32 + tile) * 4096 + perm_word(8, c64, r64)] = val;
                }
            }
}

// ---------------------------------------------------------------------------
// Fused attention + exp + row-sum (unchanged core). O epilogue writes
// tf32-rounded permuted tiles for the cp.async output GEMM.
// ---------------------------------------------------------------------------
__global__ __launch_bounds__(256, 2) void fused_attn(float* __restrict__ attn) {
    extern __shared__ uint32_t sm[];
    uint32_t* Qp = sm;            // 8192 w
    uint32_t* Kp = sm + 8192;     // 2 x 4096 w
    uint32_t* Vp = sm + 16384;    // 4096 w (reused as rs[4][128] after loop)
    uint32_t* Sp = sm + 20480;    // 8192 w

    const int tid = threadIdx.x, lane = tid & 31, wid = tid >> 5;
    const int g = lane >> 2, t4 = lane & 3;
    const int wm = (wid & 1) * 64, wn = (wid >> 1) * 16;
    const int h = blockIdx.y, mt = blockIdx.x;
    const int m0 = mt * 128;
    const int slot = wn >> 5;
    const size_t attn_base = (size_t)h * SQ * SQ;
    const uint32_t* kg = g_kp + h * 32 * 4096;
    const uint32_t* vg = g_vp + h * 32 * 4096;

    // prologue: cp.async K[0] and Q
#pragma unroll
    for (int i = 0; i < 4; i++)
        cpa16(Kp + tid * 4 + i * 1024, kg + tid * 4 + i * 1024);
    {
        const uint32_t* qg = g_qp + (h * 16 + mt) * 8192;
#pragma unroll
        for (int i = 0; i < 8; i++)
            cpa16(Qp + tid * 4 + i * 1024, qg + tid * 4 + i * 1024);
    }
    CPA_COMMIT;

    float oacc[4][2][4] = {};
    float rsum[4][2] = {};

    for (int tt = 0; tt < NT; tt++) {
        const int t0 = tt * 64;
        uint32_t* Kc = Kp + (tt & 1) * 4096;

        CPA_WAIT(0);
        __syncthreads();

        uint32_t mw[4][2];
        {
            const uint32_t* mb = g_mbits + (tt * 2 + slot) * SQ + m0;
#pragma unroll
            for (int mi = 0; mi < 4; mi++)
#pragma unroll
                for (int e2 = 0; e2 < 2; e2++)
                    mw[mi][e2] = mb[wm + mi * 16 + g + e2 * 8];
        }

#pragma unroll
        for (int i = 0; i < 4; i++)
            cpa16(Vp + tid * 4 + i * 1024, vg + tt * 4096 + tid * 4 + i * 1024);
        CPA_COMMIT;
        if (tt + 1 < NT) {
            uint32_t* Kn = Kp + ((tt + 1) & 1) * 4096;
#pragma unroll
            for (int i = 0; i < 4; i++)
                cpa16(Kn + tid * 4 + i * 1024, kg + (tt + 1) * 4096 + tid * 4 + i * 1024);
        }
        CPA_COMMIT;

        // S = Q K^T
        float sacc[4][2][4] = {};
#pragma unroll
        for (int s = 0; s < 8; s++) {
            uint4 aq[4];
#pragma unroll
            for (int mi = 0; mi < 4; mi++)
                aq[mi] = *(const uint4*)&Qp[frag_addr(8, (wm >> 4) + mi, s, g, t4)];
            uint4 bk = *(const uint4*)&Kc[frag_addr(8, wn >> 4, s, g, t4)];
#pragma unroll
            for (int mi = 0; mi < 4; mi++) {
                mma8(sacc[mi][0], aq[mi].x, aq[mi].y, aq[mi].z, aq[mi].w, bk.x, bk.z);
                mma8(sacc[mi][1], aq[mi].x, aq[mi].y, aq[mi].z, aq[mi].w, bk.y, bk.w);
            }
        }

        // epilogue: scale + mask; attn <- exp(v) streaming; Sp <- tf32(v)
#pragma unroll
        for (int mi = 0; mi < 4; mi++)
#pragma unroll
            for (int ni = 0; ni < 2; ni++)
#pragma unroll
                for (int e2 = 0; e2 < 2; e2++) {
                    int rl = wm + mi * 16 + g + e2 * 8;
                    int cl = wn + ni * 8 + t4 * 2;
                    int rg = m0 + rl, cg = t0 + cl;
                    float v0 = sacc[mi][ni][e2 * 2] * 0.125f;
                    float v1 = sacc[mi][ni][e2 * 2 + 1] * 0.125f;
                    uint32_t w = mw[mi][e2];
                    if ((w >> (cl & 31)) & 1) v0 = -1e-7f;
                    if ((w >> ((cl & 31) + 1)) & 1) v1 = -1e-7f;
                    float e0 = __expf(v0), e1 = __expf(v1);
                    __stcs((float2*)(attn + attn_base + (size_t)rg * SQ + cg),
                           make_float2(e0, e1));
                    rsum[mi][e2] += e0 + e1;
                    Sp[perm_word(8, rl, cl)] = f2tf(v0);
                    Sp[perm_word(8, rl, cl + 1)] = f2tf(v1);
                }

        CPA_WAIT(1);
        __syncthreads();

        // O += S @ V
#pragma unroll
        for (int s = 0; s < 8; s++) {
            uint4 as[4];
#pragma unroll
            for (int mi = 0; mi < 4; mi++)
                as[mi] = *(const uint4*)&Sp[frag_addr(8, (wm >> 4) + mi, s, g, t4)];
            uint4 bv = *(const uint4*)&Vp[frag_addr(8, wn >> 4, s, g, t4)];
#pragma unroll
            for (int mi = 0; mi < 4; mi++) {
                mma8(oacc[mi][0], as[mi].x, as[mi].y, as[mi].z, as[mi].w, bv.x, bv.z);
                mma8(oacc[mi][1], as[mi].x, as[mi].y, as[mi].z, as[mi].w, bv.y, bv.w);
            }
        }
    }

    // O epilogue: tf32-round + permuted tile write for output GEMM
#pragma unroll
    for (int mi = 0; mi < 4; mi++)
#pragma unroll
        for (int ni = 0; ni < 2; ni++)
#pragma unroll
            for (int e = 0; e < 4; e++) {
                int rl = wm + mi * 16 + g + (e >> 1) * 8;
                int col = wn + ni * 8 + t4 * 2 + (e & 1);  // 0..63
                int kt = h * 2 + (col >> 5);
                g_op[(mt * 32 + kt) * 4096 + perm_word(4, rl, col & 31)] =
                    f2tf(oacc[mi][ni][e]);
            }

    // deterministic row-sum reduction
    __syncthreads();
    float* rs = (float*)Vp;
    rs[tid] = 0.f;
    rs[tid + 256] = 0.f;
    __syncthreads();
#pragma unroll
    for (int mi = 0; mi < 4; mi++)
#pragma unroll
        for (int e2 = 0; e2 < 2; e2++) {
            float r = rsum[mi][e2];
            r += __shfl_xor_sync(0xffffffffu, r, 1);
            r += __shfl_xor_sync(0xffffffffu, r, 2);
            if (t4 == 0) rs[(wid >> 1) * 128 + wm + mi * 16 + g + e2 * 8] = r;
        }
    __syncthreads();
    if (tid < 128)
        g_rsum[h * SQ + m0 + tid] =
            rs[tid] + rs[128 + tid] + rs[256 + tid] + rs[384 + tid];
}

// ---------------------------------------------------------------------------
// Heterogeneous tail: blocks 0..127 = output projection (cp.async GEMM from
// permuted g_op/Wo tiles); blocks 128+ = attn scale stream.
// ---------------------------------------------------------------------------
__global__ __launch_bounds__(256, 2) void out_scale(float* __restrict__ C,
                                                    float* __restrict__ attn) {
    extern __shared__ uint32_t sm[];
    const int bid = blockIdx.x;
    const int tid = threadIdx.x;

    if (bid >= 128) {  // scale: 2048 blocks x 16 rows
        const int r0 = (bid - 128) * 16;
#pragma unroll 2
        for (int r = 0; r < 16; r++) {
            const int row = r0 + r;
            const float inv = 1.0f / g_rsum[row];
            float* p = attn + (size_t)row * SQ;
            float4 a = __ldcs((const float4*)(p + tid * 4));
            float4 b = __ldcs((const float4*)(p + 1024 + tid * 4));
            a.x *= inv; a.y *= inv; a.z *= inv; a.w *= inv;
            b.x *= inv; b.y *= inv; b.z *= inv; b.w *= inv;
            __stcs((float4*)(p + tid * 4), a);
            __stcs((float4*)(p + 1024 + tid * 4), b);
        }
        return;
    }

    const int mt = bid >> 3, nt = bid & 7;
    const int lane = tid & 31, wid = tid >> 5;
    const int g = lane >> 2, t4 = lane & 3;
    const int wm = (wid & 1) * 64, wn = (wid >> 1) * 32;
    const uint32_t* At = g_op + (size_t)(mt * 32) * 4096;
    const uint32_t* Bt = g_wp + (size_t)(3 * 256 + nt * 32) * 4096;

#pragma unroll
    for (int i = 0; i < 4; i++) {
        cpa16(sm + tid * 4 + i * 1024, At + tid * 4 + i * 1024);
        cpa16(sm + 4096 + tid * 4 + i * 1024, Bt + tid * 4 + i * 1024);
    }
    CPA_COMMIT;

    float acc[4][4][4] = {};

    for (int kt = 0; kt < 32; kt++) {
        uint32_t* S = sm + (kt & 1) * 8192;
        CPA_WAIT(0);
        __syncthreads();
        if (kt + 1 < 32) {
            uint32_t* Nx = sm + ((kt + 1) & 1) * 8192;
            const uint32_t* An = At + (kt + 1) * 4096;
            const uint32_t* Bn = Bt + (kt + 1) * 4096;
#pragma unroll
            for (int i = 0; i < 4; i++) {
                cpa16(Nx + tid * 4 + i * 1024, An + tid * 4 + i * 1024);
                cpa16(Nx + 4096 + tid * 4 + i * 1024, Bn + tid * 4 + i * 1024);
            }
            CPA_COMMIT;
        }
#pragma unroll
        for (int s = 0; s < 4; s++) {
            uint4 av[4], bv[2];
#pragma unroll
            for (int mi = 0; mi < 4; mi++)
                av[mi] = *(const uint4*)&S[frag_addr(4, (wm >> 4) + mi, s, g, t4)];
#pragma unroll
            for (int bi = 0; bi < 2; bi++)
                bv[bi] = *(const uint4*)&S[4096 + frag_addr(4, (wn >> 4) + bi, s, g, t4)];
#pragma unroll
            for (int mi = 0; mi < 4; mi++)
#pragma unroll
                for (int bi = 0; bi < 2; bi++) {
                    mma8(acc[mi][bi * 2], av[mi].x, av[mi].y, av[mi].z, av[mi].w,
                         bv[bi].x, bv[bi].z);
                    mma8(acc[mi][bi * 2 + 1], av[mi].x, av[mi].y, av[mi].z, av[mi].w,
                         bv[bi].y, bv[bi].w);
                }
        }
    }

#pragma unroll
    for (int mi = 0; mi < 4; mi++)
#pragma unroll
        for (int ni = 0; ni < 4; ni++)
#pragma unroll
            for (int e = 0; e < 4; e++) {
                int row = mt * 128 + wm + mi * 16 + g + (e >> 1) * 8;
                int col = nt * 128 + wn + ni * 8 + t4 * 2 + (e & 1);
                C[(size_t)row * DM + col] = acc[mi][ni][e];
            }
}

extern "C" void kernel_launch(void* const* d_in, const int* in_sizes, int n_in,
                              void* d_out, int out_size) {
    const float* q_in = (const float*)d_in[0];
    const float* k_in = (const float*)d_in[1];
    const float* v_in = (const float*)d_in[2];
    const int* mask = (const int*)d_in[3];
    const float* Wq = (const float*)d_in[4];
    const float* Wk = (const float*)d_in[5];
    const float* Wv = (const float*)d_in[6];
    const float* Wo = (const float*)d_in[7];

    float* out = (float*)d_out;           // [S, DM]
    float* attn = out + (size_t)SQ * DM;  // [H, S, S]

    static int smem_set = 0;
    if (!smem_set) {
        cudaFuncSetAttribute(fused_attn, cudaFuncAttributeMaxDynamicSharedMemorySize,
                             114688);
        cudaFuncSetAttribute(gemm_qkv, cudaFuncAttributeMaxDynamicSharedMemorySize,
                             65536);
        cudaFuncSetAttribute(out_scale, cudaFuncAttributeMaxDynamicSharedMemorySize,
                             65536);
        smem_set = 1;
    }

    prep<<<2816, 256>>>(q_in, k_in, v_in, Wq, Wk, Wv, Wo, mask);

    dim3 gQKV(8, 16, 3);
    gemm_qkv<<<gQKV, 256, 65536>>>();

    dim3 gFused(SQ / 128, NH, 1);  // (16, 16)
    fused_attn<<<gFused, 256, 114688>>>(attn);

    out_scale<<<128 + 2048, 256, 65536>>>(out, attn);
}